// round 1
// baseline (speedup 1.0000x reference)
#include <cuda_runtime.h>
#include <math.h>

#define HH 1024
#define WW 1024
#define BBATCH 8
#define PLANE (HH*WW)          // 1<<20
#define NPIX (BBATCH*PLANE)    // 8<<20

// Scratch (static device arrays: allowed; runtime alloc is not)
__device__ float g_E[NPIX];    // edge_soft
__device__ float g_A[NPIX];    // ping
__device__ float g_B2[NPIX];   // pong
__device__ float g_acc[3];     // mask_sum, chroma_sum, hue_sum

__device__ __forceinline__ float4 ld4(const float* p){ return *reinterpret_cast<const float4*>(p); }
__device__ __forceinline__ void st4(float* p, float4 v){ *reinterpret_cast<float4*>(p) = v; }

template<bool M>
__device__ __forceinline__ float rop(float a, float b){ return M ? fmaxf(a,b) : fminf(a,b); }

// ---------------------------------------------------------------------------
// Pass 1: Sobel edge (zero-padded), |gx|+|gy|, max over channels, clip(/0.5,0,1)
// Separable Sobel: s = t(y-1)+2t(y)+t(y+1); d = t(y+1)-t(y-1)
//   gx = s(x+1)-s(x-1);  gy = d(x-1)+2d(x)+d(x+1)
// One block per (batch,row); thread handles 4 consecutive x.
// ---------------------------------------------------------------------------
__global__ void __launch_bounds__(256) edge_kernel(const float* __restrict__ t)
{
    int y  = blockIdx.x & (HH-1);
    int b  = blockIdx.x >> 10;
    int x0 = threadIdx.x << 2;
    const float* base = t + (size_t)b*3*PLANE + (size_t)y*WW;

    float g0=0.f, g1=0.f, g2=0.f, g3=0.f;

    #pragma unroll
    for (int c = 0; c < 3; c++) {
        const float* p = base + (size_t)c*PLANE;
        float a[6], bm[6], cm[6];

        // middle row (always valid)
        bm[0] = (x0 > 0) ? p[x0-1] : 0.f;
        { float4 v = ld4(p + x0); bm[1]=v.x; bm[2]=v.y; bm[3]=v.z; bm[4]=v.w; }
        bm[5] = (x0+4 < WW) ? p[x0+4] : 0.f;

        if (y > 0) {
            const float* q = p - WW;
            a[0] = (x0 > 0) ? q[x0-1] : 0.f;
            float4 u = ld4(q + x0); a[1]=u.x; a[2]=u.y; a[3]=u.z; a[4]=u.w;
            a[5] = (x0+4 < WW) ? q[x0+4] : 0.f;
        } else {
            #pragma unroll
            for (int i=0;i<6;i++) a[i]=0.f;
        }
        if (y < HH-1) {
            const float* q = p + WW;
            cm[0] = (x0 > 0) ? q[x0-1] : 0.f;
            float4 u = ld4(q + x0); cm[1]=u.x; cm[2]=u.y; cm[3]=u.z; cm[4]=u.w;
            cm[5] = (x0+4 < WW) ? q[x0+4] : 0.f;
        } else {
            #pragma unroll
            for (int i=0;i<6;i++) cm[i]=0.f;
        }

        float s[6], d[6];
        #pragma unroll
        for (int i=0;i<6;i++){ s[i] = fmaf(2.f, bm[i], a[i]+cm[i]); d[i] = cm[i]-a[i]; }

        float gg[4];
        #pragma unroll
        for (int j=0;j<4;j++){
            float gx = s[j+2] - s[j];
            float gy = fmaf(2.f, d[j+1], d[j]+d[j+2]);
            gg[j] = fabsf(gx) + fabsf(gy);
        }
        g0 = fmaxf(g0, gg[0]); g1 = fmaxf(g1, gg[1]);
        g2 = fmaxf(g2, gg[2]); g3 = fmaxf(g3, gg[3]);
    }

    float4 o;
    o.x = fminf(g0*2.f, 1.f);  // /EDGE_THRESHOLD(0.5), clip to [0,1]; grad>=0
    o.y = fminf(g1*2.f, 1.f);
    o.z = fminf(g2*2.f, 1.f);
    o.w = fminf(g3*2.f, 1.f);
    st4(g_E + (size_t)blockIdx.x*WW + x0, o);
}

// ---------------------------------------------------------------------------
// Horizontal 11-tap pool. Shared-prefix: common = reduce a[3..10]
// ---------------------------------------------------------------------------
template<bool M>
__device__ __forceinline__ void hpool11_body(const float* __restrict__ in, float* __restrict__ out)
{
    int row = blockIdx.x;
    const float* p = in + (size_t)row*WW;
    int x0 = threadIdx.x << 2;
    float a[14];   // positions x0-5 .. x0+8
    if (x0 >= 8 && x0 <= WW-12) {
        float4 v0 = ld4(p+x0-8), v1 = ld4(p+x0-4), v2 = ld4(p+x0), v3 = ld4(p+x0+4), v4 = ld4(p+x0+8);
        a[0]=v0.w;
        a[1]=v1.x; a[2]=v1.y; a[3]=v1.z; a[4]=v1.w;
        a[5]=v2.x; a[6]=v2.y; a[7]=v2.z; a[8]=v2.w;
        a[9]=v3.x; a[10]=v3.y; a[11]=v3.z; a[12]=v3.w;
        a[13]=v4.x;
    } else {
        #pragma unroll
        for (int i=0;i<14;i++){
            int xx = x0-5+i; xx = xx < 0 ? 0 : (xx > WW-1 ? WW-1 : xx);
            a[i] = p[xx];
        }
    }
    float C = a[3];
    #pragma unroll
    for (int i=4;i<=10;i++) C = rop<M>(C, a[i]);
    float t12 = rop<M>(a[1],  a[2]);
    float t23 = rop<M>(a[11], a[12]);
    float4 o;
    o.x = rop<M>(C, rop<M>(a[0], t12));            // a[0..10]
    o.y = rop<M>(C, rop<M>(t12,  a[11]));          // a[1..11]
    o.z = rop<M>(rop<M>(C, a[2]),  t23);           // a[2..12]
    o.w = rop<M>(rop<M>(C, a[13]), t23);           // a[3..13]
    st4(out + (size_t)row*WW + x0, o);
}

__global__ void __launch_bounds__(256) k_hmax11(){ hpool11_body<true >(g_E,  g_A); }
__global__ void __launch_bounds__(256) k_hmin11(){ hpool11_body<false>(g_B2, g_A); }

// ---------------------------------------------------------------------------
// Vertical 11-tap pool (clamped rows == inf-padded reduce_window)
// ---------------------------------------------------------------------------
template<bool M>
__device__ __forceinline__ void vpool11_body(const float* __restrict__ in, float* __restrict__ out)
{
    int y  = blockIdx.x & (HH-1);
    int b  = blockIdx.x >> 10;
    int x0 = threadIdx.x << 2;
    const float* base = in + (size_t)b*PLANE + x0;
    int yy0 = y-5 < 0 ? 0 : y-5;
    float4 r = ld4(base + (size_t)yy0*WW);
    #pragma unroll
    for (int dy=-4; dy<=5; dy++){
        int yy = y+dy; yy = yy < 0 ? 0 : (yy > HH-1 ? HH-1 : yy);
        float4 v = ld4(base + (size_t)yy*WW);
        r.x = rop<M>(r.x, v.x); r.y = rop<M>(r.y, v.y);
        r.z = rop<M>(r.z, v.z); r.w = rop<M>(r.w, v.w);
    }
    st4(out + (size_t)b*PLANE + (size_t)y*WW + x0, r);
}

__global__ void __launch_bounds__(256) k_vmax11(){ vpool11_body<true >(g_A, g_B2); }
__global__ void __launch_bounds__(256) k_vmin11(){ vpool11_body<false>(g_A, g_B2); }

// ---------------------------------------------------------------------------
// mask = relu(closed - edge) fused with horizontal 5-tap max
// ---------------------------------------------------------------------------
__global__ void __launch_bounds__(256) k_maskh5()
{
    int row = blockIdx.x;
    const float* pc = g_B2 + (size_t)row*WW;  // closed
    const float* pe = g_E  + (size_t)row*WW;  // edge_soft
    int x0 = threadIdx.x << 2;
    float m[8];   // positions x0-2 .. x0+5
    if (x0 >= 4 && x0 <= WW-8) {
        float4 c0 = ld4(pc+x0-4), c1 = ld4(pc+x0), c2 = ld4(pc+x0+4);
        float4 e0 = ld4(pe+x0-4), e1 = ld4(pe+x0), e2 = ld4(pe+x0+4);
        m[0]=fmaxf(c0.z-e0.z,0.f); m[1]=fmaxf(c0.w-e0.w,0.f);
        m[2]=fmaxf(c1.x-e1.x,0.f); m[3]=fmaxf(c1.y-e1.y,0.f);
        m[4]=fmaxf(c1.z-e1.z,0.f); m[5]=fmaxf(c1.w-e1.w,0.f);
        m[6]=fmaxf(c2.x-e2.x,0.f); m[7]=fmaxf(c2.y-e2.y,0.f);
    } else {
        #pragma unroll
        for (int i=0;i<8;i++){
            int xx = x0-2+i; xx = xx < 0 ? 0 : (xx > WW-1 ? WW-1 : xx);
            m[i] = fmaxf(pc[xx]-pe[xx], 0.f);
        }
    }
    float C   = fmaxf(m[3], m[4]);
    float t12 = fmaxf(m[1], m[2]);
    float t56 = fmaxf(m[5], m[6]);
    float4 o;
    o.x = fmaxf(C, fmaxf(m[0], t12));   // m[0..4]
    o.y = fmaxf(C, fmaxf(t12,  m[5]));  // m[1..5]
    o.z = fmaxf(fmaxf(C, m[2]), t56);   // m[2..6]
    o.w = fmaxf(fmaxf(C, m[7]), t56);   // m[3..7]
    st4(g_A + (size_t)row*WW + x0, o);
}

__global__ void __launch_bounds__(256) k_vmax5()
{
    int y  = blockIdx.x & (HH-1);
    int b  = blockIdx.x >> 10;
    int x0 = threadIdx.x << 2;
    const float* base = g_A + (size_t)b*PLANE + x0;
    int yy0 = y-2 < 0 ? 0 : y-2;
    float4 r = ld4(base + (size_t)yy0*WW);
    #pragma unroll
    for (int dy=-1; dy<=2; dy++){
        int yy = y+dy; yy = yy < 0 ? 0 : (yy > HH-1 ? HH-1 : yy);
        float4 v = ld4(base + (size_t)yy*WW);
        r.x = fmaxf(r.x, v.x); r.y = fmaxf(r.y, v.y);
        r.z = fmaxf(r.z, v.z); r.w = fmaxf(r.w, v.w);
    }
    st4(g_B2 + (size_t)b*PLANE + (size_t)y*WW + x0, r);
}

// ---------------------------------------------------------------------------
// Loss: OKLab a,b for pred & target only where mask > 0 (term is *mask, so
// skipping mask==0 is exact). mask_sum always accumulated.
// ---------------------------------------------------------------------------
__device__ __forceinline__ float s2l(float x)
{
    x = fminf(fmaxf(x, 0.f), 1.f);
    return (x <= 0.04045f) ? x * (1.f/12.92f)
                           : powf((x + 0.055f) * (1.f/1.055f), 2.4f);
}

__device__ __forceinline__ void oklab_ab(float r, float g, float bl, float& A, float& Bc)
{
    float lr = s2l(r), lg = s2l(g), lb = s2l(bl);
    float l = 0.4122214708f*lr + 0.5363325363f*lg + 0.0514459929f*lb;
    float m = 0.2119034982f*lr + 0.6806995451f*lg + 0.1073969566f*lb;
    float s = 0.0883024619f*lr + 0.2817188376f*lg + 0.6299787005f*lb;
    l = cbrtf(fmaxf(l, 1e-10f));
    m = cbrtf(fmaxf(m, 1e-10f));
    s = cbrtf(fmaxf(s, 1e-10f));
    A  = 1.9779984951f*l - 2.428592205f*m + 0.4505937099f*s;
    Bc = 0.0259040371f*l + 0.7827717662f*m - 0.808675766f*s;
}

__global__ void __launch_bounds__(256) k_loss(const float* __restrict__ pred,
                                              const float* __restrict__ tgt)
{
    const int NG = NPIX / 4;
    float msum = 0.f, chroma = 0.f, hue = 0.f;

    for (int gidx = blockIdx.x*blockDim.x + threadIdx.x; gidx < NG;
         gidx += gridDim.x*blockDim.x)
    {
        int pix = gidx << 2;
        float4 mk = ld4(g_B2 + pix);
        msum += (mk.x + mk.y) + (mk.z + mk.w);
        if (mk.x > 0.f || mk.y > 0.f || mk.z > 0.f || mk.w > 0.f) {
            int b   = pix >> 20;           // PLANE == 1<<20
            int rem = pix & (PLANE-1);
            size_t base = (size_t)b*3*PLANE + rem;
            float mv[4] = {mk.x, mk.y, mk.z, mk.w};
            #pragma unroll 1
            for (int j=0;j<4;j++){
                float m = mv[j];
                if (m > 0.f) {
                    float pa,pb,ta,tb;
                    oklab_ab(pred[base+j], pred[base+j+PLANE], pred[base+j+2*PLANE], pa, pb);
                    oklab_ab(tgt [base+j], tgt [base+j+PLANE], tgt [base+j+2*PLANE], ta, tb);
                    float Cp = sqrtf(fmaf(pa,pa, pb*pb) + 1e-12f);
                    float Cg = sqrtf(fmaf(ta,ta, tb*tb) + 1e-12f);
                    chroma += fabsf(Cp - Cg) * m;
                    float cosd = (pa*ta + pb*tb) / (Cp*Cg + 1e-12f);
                    cosd = fminf(fmaxf(cosd, -1.f), 1.f);
                    hue += fmaxf(Cg, 0.01f) * (1.f - cosd) * m;
                }
            }
        }
    }

    // warp reduce
    #pragma unroll
    for (int o=16; o; o>>=1){
        msum   += __shfl_xor_sync(0xffffffffu, msum,   o);
        chroma += __shfl_xor_sync(0xffffffffu, chroma, o);
        hue    += __shfl_xor_sync(0xffffffffu, hue,    o);
    }
    __shared__ float sm[3][8];
    int w = threadIdx.x >> 5, lane = threadIdx.x & 31;
    if (lane == 0){ sm[0][w]=msum; sm[1][w]=chroma; sm[2][w]=hue; }
    __syncthreads();
    if (threadIdx.x == 0){
        float a=0.f, c=0.f, h=0.f;
        #pragma unroll
        for (int i=0;i<8;i++){ a+=sm[0][i]; c+=sm[1][i]; h+=sm[2][i]; }
        atomicAdd(&g_acc[0], a);
        atomicAdd(&g_acc[1], c);
        atomicAdd(&g_acc[2], h);
    }
}

__global__ void k_zero(){ if (threadIdx.x < 3) g_acc[threadIdx.x] = 0.f; }

__global__ void k_fin(float* out)
{
    float ms = fmaxf(g_acc[0], 1.f);
    out[0] = g_acc[1]/ms + 2.f*(g_acc[2]/ms);
}

// ---------------------------------------------------------------------------
extern "C" void kernel_launch(void* const* d_in, const int* in_sizes, int n_in,
                              void* d_out, int out_size)
{
    const float* pred = (const float*)d_in[0];
    const float* tgt  = (const float*)d_in[1];
    float* out = (float*)d_out;

    const int rows = BBATCH*HH;   // 8192 blocks, one per (batch,row)
    dim3 blk(256);

    k_zero     <<<1, 32>>>();
    edge_kernel<<<rows, blk>>>(tgt);      // target -> g_E
    k_hmax11   <<<rows, blk>>>();         // g_E  -> g_A
    k_vmax11   <<<rows, blk>>>();         // g_A  -> g_B2 (dilated)
    k_hmin11   <<<rows, blk>>>();         // g_B2 -> g_A
    k_vmin11   <<<rows, blk>>>();         // g_A  -> g_B2 (closed)
    k_maskh5   <<<rows, blk>>>();         // (g_B2, g_E) -> g_A
    k_vmax5    <<<rows, blk>>>();         // g_A  -> g_B2 (final mask)
    k_loss     <<<1184, blk>>>(pred, tgt);
    k_fin      <<<1, 1>>>(out);
}

// round 3
// speedup vs baseline: 1.1130x; 1.1130x over previous
#include <cuda_runtime.h>
#include <math.h>

#define HH 1024
#define WW 1024
#define BBATCH 8
#define PLANE (HH*WW)          // 1<<20
#define NPIX (BBATCH*PLANE)    // 8<<20

// Scratch (static device arrays: allowed; runtime alloc is not)
__device__ float g_E[NPIX];    // edge_soft
__device__ float g_A[NPIX];    // ping
__device__ float g_B2[NPIX];   // pong
__device__ float g_acc[3];     // mask_sum, chroma_sum, hue_sum

__device__ __forceinline__ float4 ld4(const float* p){ return *reinterpret_cast<const float4*>(p); }
__device__ __forceinline__ void st4(float* p, float4 v){ *reinterpret_cast<float4*>(p) = v; }

template<bool M>
__device__ __forceinline__ float rop(float a, float b){ return M ? fmaxf(a,b) : fminf(a,b); }

// ---------------------------------------------------------------------------
// Pass 1: Sobel edge (zero-padded), |gx|+|gy|, max over channels, clip(/0.5,0,1)
// Separable Sobel: s = t(y-1)+2t(y)+t(y+1); d = t(y+1)-t(y-1)
//   gx = s(x+1)-s(x-1);  gy = d(x-1)+2d(x)+d(x+1)
// ET output rows per block via 3-row register ring per channel.
// ---------------------------------------------------------------------------
#define ET 8   // rows per block in edge kernel

__device__ __forceinline__ void load_row6(const float* p, int x0, float* r)
{
    // positions x0-1 .. x0+4, zero OOB in x
    r[0] = (x0 > 0) ? p[x0-1] : 0.f;
    float4 v = ld4(p + x0); r[1]=v.x; r[2]=v.y; r[3]=v.z; r[4]=v.w;
    r[5] = (x0+4 < WW) ? p[x0+4] : 0.f;
}

__device__ __forceinline__ void zero_row6(float* r)
{
    #pragma unroll
    for (int i=0;i<6;i++) r[i]=0.f;
}

__global__ void __launch_bounds__(256) edge_kernel(const float* __restrict__ t)
{
    int x0  = threadIdx.x << 2;
    int grp = blockIdx.x;
    int b   = grp / (HH/ET);
    int y0  = (grp % (HH/ET)) * ET;

    float g[ET][4];
    #pragma unroll
    for (int k=0;k<ET;k++){ g[k][0]=0.f; g[k][1]=0.f; g[k][2]=0.f; g[k][3]=0.f; }

    #pragma unroll
    for (int c = 0; c < 3; c++) {
        const float* p = t + (size_t)b*3*PLANE + (size_t)c*PLANE;
        float row[3][6];
        if (y0 > 0) load_row6(p + (size_t)(y0-1)*WW, x0, row[0]);
        else        zero_row6(row[0]);
        load_row6(p + (size_t)y0*WW, x0, row[1]);

        #pragma unroll
        for (int k = 0; k < ET; k++) {
            int ynext = y0 + k + 1;
            float* nr = row[(k+2)%3];
            if (ynext <= HH-1) load_row6(p + (size_t)ynext*WW, x0, nr);
            else               zero_row6(nr);

            const float* a  = row[ k   %3];
            const float* bm = row[(k+1)%3];
            const float* cm = row[(k+2)%3];

            float s[6], d[6];
            #pragma unroll
            for (int i=0;i<6;i++){ s[i] = fmaf(2.f, bm[i], a[i]+cm[i]); d[i] = cm[i]-a[i]; }
            #pragma unroll
            for (int j=0;j<4;j++){
                float gx = s[j+2] - s[j];
                float gy = fmaf(2.f, d[j+1], d[j]+d[j+2]);
                g[k][j] = fmaxf(g[k][j], fabsf(gx) + fabsf(gy));
            }
        }
    }

    float* obase = g_E + (size_t)b*PLANE + x0;
    #pragma unroll
    for (int k=0;k<ET;k++){
        float4 o;
        o.x = fminf(g[k][0]*2.f, 1.f);
        o.y = fminf(g[k][1]*2.f, 1.f);
        o.z = fminf(g[k][2]*2.f, 1.f);
        o.w = fminf(g[k][3]*2.f, 1.f);
        st4(obase + (size_t)(y0+k)*WW, o);
    }
}

// ---------------------------------------------------------------------------
// Horizontal 11-tap pool. Shared-prefix: common = reduce a[3..10]
// ---------------------------------------------------------------------------
template<bool M>
__device__ __forceinline__ void hpool11_body(const float* __restrict__ in, float* __restrict__ out)
{
    int row = blockIdx.x;
    const float* p = in + (size_t)row*WW;
    int x0 = threadIdx.x << 2;
    float a[14];   // positions x0-5 .. x0+8
    if (x0 >= 8 && x0 <= WW-12) {
        float4 v0 = ld4(p+x0-8), v1 = ld4(p+x0-4), v2 = ld4(p+x0), v3 = ld4(p+x0+4), v4 = ld4(p+x0+8);
        a[0]=v0.w;
        a[1]=v1.x; a[2]=v1.y; a[3]=v1.z; a[4]=v1.w;
        a[5]=v2.x; a[6]=v2.y; a[7]=v2.z; a[8]=v2.w;
        a[9]=v3.x; a[10]=v3.y; a[11]=v3.z; a[12]=v3.w;
        a[13]=v4.x;
    } else {
        #pragma unroll
        for (int i=0;i<14;i++){
            int xx = x0-5+i; xx = xx < 0 ? 0 : (xx > WW-1 ? WW-1 : xx);
            a[i] = p[xx];
        }
    }
    float C = a[3];
    #pragma unroll
    for (int i=4;i<=10;i++) C = rop<M>(C, a[i]);
    float t12 = rop<M>(a[1],  a[2]);
    float t23 = rop<M>(a[11], a[12]);
    float4 o;
    o.x = rop<M>(C, rop<M>(a[0], t12));            // a[0..10]
    o.y = rop<M>(C, rop<M>(t12,  a[11]));          // a[1..11]
    o.z = rop<M>(rop<M>(C, a[2]),  t23);           // a[2..12]
    o.w = rop<M>(rop<M>(C, a[13]), t23);           // a[3..13]
    st4(out + (size_t)row*WW + x0, o);
}

__global__ void __launch_bounds__(256) k_hmax11(){ hpool11_body<true >(g_E,  g_A); }
__global__ void __launch_bounds__(256) k_hmin11(){ hpool11_body<false>(g_B2, g_A); }

// ---------------------------------------------------------------------------
// Vertical K-tap pool, T output rows per block via K-deep register ring.
// Loads (T+K-1)/T rows per output row instead of K.
// Clamped rows == inf-padded reduce_window for max/min.
// ---------------------------------------------------------------------------
template<bool M, int K, int T>
__device__ __forceinline__ void vpool_body(const float* __restrict__ in, float* __restrict__ out)
{
    constexpr int HALO = K/2;
    int x0  = threadIdx.x << 2;
    int grp = blockIdx.x;
    int b   = grp / (HH/T);
    int y0  = (grp % (HH/T)) * T;
    const float* base  = in  + (size_t)b*PLANE + x0;
    float*       obase = out + (size_t)b*PLANE + x0;

    float4 r[K];
    #pragma unroll
    for (int i = 0; i < K-1; i++) {
        int yy = y0 - HALO + i; yy = yy < 0 ? 0 : yy;
        r[i] = ld4(base + (size_t)yy*WW);
    }
    #pragma unroll
    for (int k = 0; k < T; k++) {
        int yy = y0 + k + HALO; yy = yy > HH-1 ? HH-1 : yy;
        r[(K-1+k) % K] = ld4(base + (size_t)yy*WW);
        float4 o = r[0];
        #pragma unroll
        for (int i=1;i<K;i++){
            o.x = rop<M>(o.x, r[i].x); o.y = rop<M>(o.y, r[i].y);
            o.z = rop<M>(o.z, r[i].z); o.w = rop<M>(o.w, r[i].w);
        }
        st4(obase + (size_t)(y0+k)*WW, o);
    }
}

#define VT 16  // output rows per block for vertical pools

__global__ void __launch_bounds__(256) k_vmax11(){ vpool_body<true , 11, VT>(g_A, g_B2); }
__global__ void __launch_bounds__(256) k_vmin11(){ vpool_body<false, 11, VT>(g_A, g_B2); }
__global__ void __launch_bounds__(256) k_vmax5 (){ vpool_body<true ,  5, VT>(g_A, g_B2); }

// ---------------------------------------------------------------------------
// mask = relu(closed - edge) fused with horizontal 5-tap max
// ---------------------------------------------------------------------------
__global__ void __launch_bounds__(256) k_maskh5()
{
    int row = blockIdx.x;
    const float* pc = g_B2 + (size_t)row*WW;  // closed
    const float* pe = g_E  + (size_t)row*WW;  // edge_soft
    int x0 = threadIdx.x << 2;
    float m[8];   // positions x0-2 .. x0+5
    if (x0 >= 4 && x0 <= WW-8) {
        float4 c0 = ld4(pc+x0-4), c1 = ld4(pc+x0), c2 = ld4(pc+x0+4);
        float4 e0 = ld4(pe+x0-4), e1 = ld4(pe+x0), e2 = ld4(pe+x0+4);
        m[0]=fmaxf(c0.z-e0.z,0.f); m[1]=fmaxf(c0.w-e0.w,0.f);
        m[2]=fmaxf(c1.x-e1.x,0.f); m[3]=fmaxf(c1.y-e1.y,0.f);
        m[4]=fmaxf(c1.z-e1.z,0.f); m[5]=fmaxf(c1.w-e1.w,0.f);
        m[6]=fmaxf(c2.x-e2.x,0.f); m[7]=fmaxf(c2.y-e2.y,0.f);
    } else {
        #pragma unroll
        for (int i=0;i<8;i++){
            int xx = x0-2+i; xx = xx < 0 ? 0 : (xx > WW-1 ? WW-1 : xx);
            m[i] = fmaxf(pc[xx]-pe[xx], 0.f);
        }
    }
    float C   = fmaxf(m[3], m[4]);
    float t12 = fmaxf(m[1], m[2]);
    float t56 = fmaxf(m[5], m[6]);
    float4 o;
    o.x = fmaxf(C, fmaxf(m[0], t12));   // m[0..4]
    o.y = fmaxf(C, fmaxf(t12,  m[5]));  // m[1..5]
    o.z = fmaxf(fmaxf(C, m[2]), t56);   // m[2..6]
    o.w = fmaxf(fmaxf(C, m[7]), t56);   // m[3..7]
    st4(g_A + (size_t)row*WW + x0, o);
}

// ---------------------------------------------------------------------------
// Loss: OKLab a,b for pred & target only where mask > 0 (term is *mask, so
// skipping mask==0 is exact). mask_sum always accumulated.
// ---------------------------------------------------------------------------
__device__ __forceinline__ float s2l(float x)
{
    x = fminf(fmaxf(x, 0.f), 1.f);
    return (x <= 0.04045f) ? x * (1.f/12.92f)
                           : powf((x + 0.055f) * (1.f/1.055f), 2.4f);
}

__device__ __forceinline__ void oklab_ab(float r, float g, float bl, float& A, float& Bc)
{
    float lr = s2l(r), lg = s2l(g), lb = s2l(bl);
    float l = 0.4122214708f*lr + 0.5363325363f*lg + 0.0514459929f*lb;
    float m = 0.2119034982f*lr + 0.6806995451f*lg + 0.1073969566f*lb;
    float s = 0.0883024619f*lr + 0.2817188376f*lg + 0.6299787005f*lb;
    l = cbrtf(fmaxf(l, 1e-10f));
    m = cbrtf(fmaxf(m, 1e-10f));
    s = cbrtf(fmaxf(s, 1e-10f));
    A  = 1.9779984951f*l - 2.428592205f*m + 0.4505937099f*s;
    Bc = 0.0259040371f*l + 0.7827717662f*m - 0.808675766f*s;
}

__global__ void __launch_bounds__(256) k_loss(const float* __restrict__ pred,
                                              const float* __restrict__ tgt)
{
    const int NG = NPIX / 4;
    float msum = 0.f, chroma = 0.f, hue = 0.f;

    for (int gidx = blockIdx.x*blockDim.x + threadIdx.x; gidx < NG;
         gidx += gridDim.x*blockDim.x)
    {
        int pix = gidx << 2;
        float4 mk = ld4(g_B2 + pix);
        msum += (mk.x + mk.y) + (mk.z + mk.w);
        if (mk.x > 0.f || mk.y > 0.f || mk.z > 0.f || mk.w > 0.f) {
            int b   = pix >> 20;           // PLANE == 1<<20
            int rem = pix & (PLANE-1);
            size_t base = (size_t)b*3*PLANE + rem;
            float mv[4] = {mk.x, mk.y, mk.z, mk.w};
            #pragma unroll 1
            for (int j=0;j<4;j++){
                float m = mv[j];
                if (m > 0.f) {
                    float pa,pb,ta,tb;
                    oklab_ab(pred[base+j], pred[base+j+PLANE], pred[base+j+2*PLANE], pa, pb);
                    oklab_ab(tgt [base+j], tgt [base+j+PLANE], tgt [base+j+2*PLANE], ta, tb);
                    float Cp = sqrtf(fmaf(pa,pa, pb*pb) + 1e-12f);
                    float Cg = sqrtf(fmaf(ta,ta, tb*tb) + 1e-12f);
                    chroma += fabsf(Cp - Cg) * m;
                    float cosd = (pa*ta + pb*tb) / (Cp*Cg + 1e-12f);
                    cosd = fminf(fmaxf(cosd, -1.f), 1.f);
                    hue += fmaxf(Cg, 0.01f) * (1.f - cosd) * m;
                }
            }
        }
    }

    // warp reduce
    #pragma unroll
    for (int o=16; o; o>>=1){
        msum   += __shfl_xor_sync(0xffffffffu, msum,   o);
        chroma += __shfl_xor_sync(0xffffffffu, chroma, o);
        hue    += __shfl_xor_sync(0xffffffffu, hue,    o);
    }
    __shared__ float sm[3][8];
    int w = threadIdx.x >> 5, lane = threadIdx.x & 31;
    if (lane == 0){ sm[0][w]=msum; sm[1][w]=chroma; sm[2][w]=hue; }
    __syncthreads();
    if (threadIdx.x == 0){
        float a=0.f, c=0.f, h=0.f;
        #pragma unroll
        for (int i=0;i<8;i++){ a+=sm[0][i]; c+=sm[1][i]; h+=sm[2][i]; }
        atomicAdd(&g_acc[0], a);
        atomicAdd(&g_acc[1], c);
        atomicAdd(&g_acc[2], h);
    }
}

__global__ void k_zero(){ if (threadIdx.x < 3) g_acc[threadIdx.x] = 0.f; }

__global__ void k_fin(float* out)
{
    float ms = fmaxf(g_acc[0], 1.f);
    out[0] = g_acc[1]/ms + 2.f*(g_acc[2]/ms);
}

// ---------------------------------------------------------------------------
extern "C" void kernel_launch(void* const* d_in, const int* in_sizes, int n_in,
                              void* d_out, int out_size)
{
    const float* pred = (const float*)d_in[0];
    const float* tgt  = (const float*)d_in[1];
    float* out = (float*)d_out;

    const int rows   = BBATCH*HH;          // 8192: one block per (batch,row)
    const int egrid  = BBATCH*HH/ET;       // 1024
    const int vgrid  = BBATCH*HH/VT;       // 512
    dim3 blk(256);

    k_zero     <<<1, 32>>>();
    edge_kernel<<<egrid, blk>>>(tgt);      // target -> g_E
    k_hmax11   <<<rows,  blk>>>();         // g_E  -> g_A
    k_vmax11   <<<vgrid, blk>>>();         // g_A  -> g_B2 (dilated)
    k_hmin11   <<<rows,  blk>>>();         // g_B2 -> g_A
    k_vmin11   <<<vgrid, blk>>>();         // g_A  -> g_B2 (closed)
    k_maskh5   <<<rows,  blk>>>();         // (g_B2, g_E) -> g_A
    k_vmax5    <<<vgrid, blk>>>();         // g_A  -> g_B2 (final mask)
    k_loss     <<<1184,  blk>>>(pred, tgt);
    k_fin      <<<1, 1>>>(out);
}